// round 10
// baseline (speedup 1.0000x reference)
#include <cuda_runtime.h>

// DyDepthwiseConvAtten: B=1024, N=100, C=256, K=3
//   K1 (wcalc): half-warp per row, W streamed from L1, 4 SHFL/row.
//   K2 (conv+LN): warp per row; gamma/beta streamed from L1 (not registers)
//      so regs fit 6 blocks/SM. One-wave persistent grid = 148*6 = 888.

#define ROWS_TOTAL (1024 * 100)
#define CH 256
#define LN_EPS 1e-5f
#define GRID_1WAVE (148 * 6)

// per-row conv taps (k0,k1,k2,pad) — 1.6 MB scratch, L2-resident
__device__ float4 g_w[ROWS_TOTAL];

// ---------------- kernel 1: dynamic taps, half-warp per row ----------------
__global__ __launch_bounds__(256, 6)
void dydw_wcalc_kernel(const float* __restrict__ query,
                       const float* __restrict__ W_w,
                       const float* __restrict__ b_w)
{
    const int lane    = threadIdx.x & 31;
    const int half    = lane >> 4;
    const int warp    = (blockIdx.x * blockDim.x + threadIdx.x) >> 5;
    const int nwarps  = (gridDim.x * blockDim.x) >> 5;
    const int cbase4  = (lane & 15) * 4;

    const float4* W0 = (const float4*)W_w + cbase4;        // tap 0, this lane's 16 ch
    const float4* W1 = (const float4*)W_w + 64 + cbase4;   // tap 1
    const float4* W2 = (const float4*)W_w + 128 + cbase4;  // tap 2

    const int grp = (lane >> 2) & 3;
    const float bias = (grp < 3) ? __ldg(&b_w[grp]) : 0.0f;

    for (int rp = warp * 2; rp < ROWS_TOTAL; rp += 2 * nwarps) {
        const int row = rp + half;
        const float4* qrow = (const float4*)(query + (size_t)row * CH);

        // issue all 4 q loads up front (MLP=4, streaming: read-once)
        float4 q4[4];
        #pragma unroll
        for (int i = 0; i < 4; i++) q4[i] = __ldcs(&qrow[cbase4 + i]);

        float s0 = 0.f, s1 = 0.f, s2 = 0.f;
        #pragma unroll
        for (int i = 0; i < 4; i++) {
            const float4 a = __ldg(&W0[i]);    // L1-resident (3KB total)
            const float4 b = __ldg(&W1[i]);
            const float4 c = __ldg(&W2[i]);
            const float4 q = q4[i];
            s0 = fmaf(q.x, a.x, fmaf(q.y, a.y, fmaf(q.z, a.z, fmaf(q.w, a.w, s0))));
            s1 = fmaf(q.x, b.x, fmaf(q.y, b.y, fmaf(q.z, b.z, fmaf(q.w, b.w, s1))));
            s2 = fmaf(q.x, c.x, fmaf(q.y, c.y, fmaf(q.z, c.z, fmaf(q.w, c.w, s2))));
        }

        // butterfly {8,4}: stays within each 16-lane half
        #pragma unroll
        for (int off = 8; off >= 4; off >>= 1) {
            s0 += __shfl_xor_sync(0xffffffffu, s0, off);
            s1 += __shfl_xor_sync(0xffffffffu, s1, off);
            s2 += __shfl_xor_sync(0xffffffffu, s2, off);
        }
        // each 4-lane group (closed under xor {2,1}) finishes one tap
        float t = (grp == 0) ? s0 : (grp == 1) ? s1 : (grp == 2) ? s2 : s0;
        t += __shfl_xor_sync(0xffffffffu, t, 2);
        t += __shfl_xor_sync(0xffffffffu, t, 1);

        if ((lane & 3) == 0) {
            const float val = (grp < 3) ? (t + bias) : 0.0f;
            ((float*)&g_w[row])[grp] = val;   // 8 lanes -> 2 contiguous sectors
        }
    }
}

// ---------------- kernel 2: conv + LayerNorm ----------------
__global__ __launch_bounds__(256, 6)
void dydw_conv_ln_kernel(const float* __restrict__ value,
                         const float* __restrict__ gamma,
                         const float* __restrict__ beta,
                         float* __restrict__ out)
{
    const int lane   = threadIdx.x & 31;
    const int warp   = (blockIdx.x * blockDim.x + threadIdx.x) >> 5;
    const int nwarps = (gridDim.x * blockDim.x) >> 5;
    const int cbase4 = lane * 2;   // float4 index of this lane's 8 channels

    for (int row = warp; row < ROWS_TOTAL; row += nwarps) {
        const float4 w4 = __ldg(&g_w[row]);   // uniform: 1 wavefront (L2 hit)
        const float k0 = w4.x, k1 = w4.y, k2 = w4.z;

        const float4* vrow = (const float4*)(value + (size_t)row * CH);
        const float4 v0 = __ldcs(&vrow[cbase4 + 0]);
        const float4 v1 = __ldcs(&vrow[cbase4 + 1]);
        const float v[8] = {v0.x, v0.y, v0.z, v0.w, v1.x, v1.y, v1.z, v1.w};

        // halo for the 3-tap conv (zero pad at row edges)
        float left  = __shfl_up_sync(0xffffffffu, v[7], 1);
        float right = __shfl_down_sync(0xffffffffu, v[0], 1);
        if (lane == 0)  left = 0.f;
        if (lane == 31) right = 0.f;

        float o[8];
        float sum = 0.f, sq = 0.f;
        #pragma unroll
        for (int i = 0; i < 8; i++) {
            const float vm = (i == 0) ? left  : v[i - 1];
            const float vp = (i == 7) ? right : v[i + 1];
            o[i] = fmaf(k0, vm, fmaf(k1, v[i], k2 * vp));
            sum += o[i];
            sq = fmaf(o[i], o[i], sq);
        }

        // grouped 2-value reduce: offset 16, then halves finish different values
        const float a = sum + __shfl_xor_sync(0xffffffffu, sum, 16);
        const float b = sq  + __shfl_xor_sync(0xffffffffu, sq,  16);
        float t = (lane < 16) ? a : b;
        #pragma unroll
        for (int off = 8; off; off >>= 1)
            t += __shfl_xor_sync(0xffffffffu, t, off);
        const float tot_sum = __shfl_sync(0xffffffffu, t, 0);
        const float tot_sq  = __shfl_sync(0xffffffffu, t, 16);

        const float mean = tot_sum * (1.f / CH);
        const float var  = tot_sq * (1.f / CH) - mean * mean;
        const float rstd = rsqrtf(var + LN_EPS);

        // gamma/beta stream from L1 (1KB resident) — keeps regs under the
        // 6-blocks/SM cap instead of pinning 16 registers per thread.
        float4* orow = (float4*)(out + (size_t)row * CH);
        #pragma unroll
        for (int i = 0; i < 2; i++) {
            const float4 g = __ldg((const float4*)gamma + cbase4 + i);
            const float4 bb = __ldg((const float4*)beta + cbase4 + i);
            float4 y;
            y.x = fmaf((o[i*4+0] - mean) * rstd, g.x, bb.x);
            y.y = fmaf((o[i*4+1] - mean) * rstd, g.y, bb.y);
            y.z = fmaf((o[i*4+2] - mean) * rstd, g.z, bb.z);
            y.w = fmaf((o[i*4+3] - mean) * rstd, g.w, bb.w);
            __stcs(&orow[cbase4 + i], y);   // write-once: streaming store
        }
    }
}

extern "C" void kernel_launch(void* const* d_in, const int* in_sizes, int n_in,
                              void* d_out, int out_size)
{
    const float* query = (const float*)d_in[0];
    const float* value = (const float*)d_in[1];
    const float* W_w   = (const float*)d_in[2];
    const float* b_w   = (const float*)d_in[3];
    const float* gamma = (const float*)d_in[4];
    const float* beta  = (const float*)d_in[5];
    float* out = (float*)d_out;

    // one full wave: 148 SMs x 6 blocks of 256 threads (<=42 regs/thread)
    dydw_wcalc_kernel<<<GRID_1WAVE, 256>>>(query, W_w, b_w);
    dydw_conv_ln_kernel<<<GRID_1WAVE, 256>>>(value, gamma, beta, out);
}

// round 12
// speedup vs baseline: 1.2749x; 1.2749x over previous
#include <cuda_runtime.h>

// DyDepthwiseConvAtten: B=1024, N=100, C=256, K=3 — FUSED single kernel.
// Per row (one warp): w_k = q·W_k + b_k (grouped butterfly, 12 SHFL),
// 3-tap conv on v via halo shuffles, LayerNorm (8 SHFL).
// W, gamma, beta streamed from L1 (4KB resident) to keep regs ~44.
// One-wave persistent grid: 740 = 148 SM x 5 blocks.
// R12 fix: W tap offsets are 64/128 float4 (were wrongly 128/256).

#define ROWS_TOTAL (1024 * 100)
#define CH 256
#define LN_EPS 1e-5f
#define GRID_1WAVE 740

__global__ __launch_bounds__(256, 5)
void dydw_fused_kernel(const float* __restrict__ query,
                       const float* __restrict__ value,
                       const float* __restrict__ W_w,
                       const float* __restrict__ b_w,
                       const float* __restrict__ gamma,
                       const float* __restrict__ beta,
                       float* __restrict__ out)
{
    const int lane   = threadIdx.x & 31;
    const int warp   = (blockIdx.x * blockDim.x + threadIdx.x) >> 5;
    const int nwarps = (gridDim.x * blockDim.x) >> 5;   // 5920
    const int cb4    = lane * 2;        // float4 index of this lane's 8 channels

    const int grp = lane >> 3;          // 8-lane group: which tap it finishes
    const float bias = (grp < 3) ? __ldg(&b_w[grp]) : 0.0f;

    // W_w is [3][256] floats = 64 float4 per tap
    const float4* W0 = (const float4*)W_w + cb4;          // tap 0
    const float4* W1 = (const float4*)W_w + 64  + cb4;    // tap 1
    const float4* W2 = (const float4*)W_w + 128 + cb4;    // tap 2

    for (int row = warp; row < ROWS_TOTAL; row += nwarps) {
        // ---- loads: q + v up front (MLP=4, DRAM stream) ----
        const float4* qrow = (const float4*)(query + (size_t)row * CH);
        const float4* vrow = (const float4*)(value + (size_t)row * CH);
        const float4 q0 = qrow[cb4 + 0];
        const float4 q1 = qrow[cb4 + 1];
        const float4 v0 = vrow[cb4 + 0];
        const float4 v1 = vrow[cb4 + 1];

        // ---- dynamic taps: s_k = sum_c q[c] * W_k[c], W from L1 (3KB) ----
        float s0, s1, s2;
        {
            const float4 a0 = __ldg(&W0[0]), a1 = __ldg(&W0[1]);
            const float4 b0 = __ldg(&W1[0]), b1 = __ldg(&W1[1]);
            const float4 c0 = __ldg(&W2[0]), c1 = __ldg(&W2[1]);
            s0 = fmaf(q0.x, a0.x, fmaf(q0.y, a0.y, fmaf(q0.z, a0.z, q0.w * a0.w)));
            s0 = fmaf(q1.x, a1.x, fmaf(q1.y, a1.y, fmaf(q1.z, a1.z, fmaf(q1.w, a1.w, s0))));
            s1 = fmaf(q0.x, b0.x, fmaf(q0.y, b0.y, fmaf(q0.z, b0.z, q0.w * b0.w)));
            s1 = fmaf(q1.x, b1.x, fmaf(q1.y, b1.y, fmaf(q1.z, b1.z, fmaf(q1.w, b1.w, s1))));
            s2 = fmaf(q0.x, c0.x, fmaf(q0.y, c0.y, fmaf(q0.z, c0.z, q0.w * c0.w)));
            s2 = fmaf(q1.x, c1.x, fmaf(q1.y, c1.y, fmaf(q1.z, c1.z, fmaf(q1.w, c1.w, s2))));
        }
        // butterfly {16,8} on all three -> mod-8 class partials everywhere
        #pragma unroll
        for (int off = 16; off >= 8; off >>= 1) {
            s0 += __shfl_xor_sync(0xffffffffu, s0, off);
            s1 += __shfl_xor_sync(0xffffffffu, s1, off);
            s2 += __shfl_xor_sync(0xffffffffu, s2, off);
        }
        // each 8-lane group (closed under {4,2,1}) finishes one tap
        float t = (grp == 0) ? s0 : (grp == 1) ? s1 : (grp == 2) ? s2 : s0;
        t += __shfl_xor_sync(0xffffffffu, t, 4);
        t += __shfl_xor_sync(0xffffffffu, t, 2);
        t += __shfl_xor_sync(0xffffffffu, t, 1);
        t += bias;
        const float k0 = __shfl_sync(0xffffffffu, t, 0);
        const float k1 = __shfl_sync(0xffffffffu, t, 8);
        const float k2 = __shfl_sync(0xffffffffu, t, 16);

        // ---- 3-tap conv along channels (zero pad at row edges) ----
        const float v[8] = {v0.x, v0.y, v0.z, v0.w, v1.x, v1.y, v1.z, v1.w};
        float left  = __shfl_up_sync(0xffffffffu, v[7], 1);
        float right = __shfl_down_sync(0xffffffffu, v[0], 1);
        if (lane == 0)  left = 0.f;
        if (lane == 31) right = 0.f;

        float o[8];
        float sum = 0.f, sq = 0.f;
        #pragma unroll
        for (int i = 0; i < 8; i++) {
            const float vm = (i == 0) ? left  : v[i - 1];
            const float vp = (i == 7) ? right : v[i + 1];
            o[i] = fmaf(k0, vm, fmaf(k1, v[i], k2 * vp));
            sum += o[i];
            sq = fmaf(o[i], o[i], sq);
        }

        // ---- LayerNorm reduce: grouped 2-value butterfly (8 SHFL) ----
        const float a = sum + __shfl_xor_sync(0xffffffffu, sum, 16);
        const float b = sq  + __shfl_xor_sync(0xffffffffu, sq,  16);
        float r = (lane < 16) ? a : b;
        #pragma unroll
        for (int off = 8; off; off >>= 1)
            r += __shfl_xor_sync(0xffffffffu, r, off);
        const float tot_sum = __shfl_sync(0xffffffffu, r, 0);
        const float tot_sq  = __shfl_sync(0xffffffffu, r, 16);

        const float mean = tot_sum * (1.f / CH);
        const float var  = tot_sq * (1.f / CH) - mean * mean;
        const float rstd = rsqrtf(var + LN_EPS);

        // ---- normalize + affine; gamma/beta from L1 (1KB resident) ----
        float4* orow = (float4*)(out + (size_t)row * CH);
        #pragma unroll
        for (int i = 0; i < 2; i++) {
            const float4 g  = __ldg((const float4*)gamma + cb4 + i);
            const float4 bb = __ldg((const float4*)beta  + cb4 + i);
            float4 y;
            y.x = fmaf((o[i*4+0] - mean) * rstd, g.x, bb.x);
            y.y = fmaf((o[i*4+1] - mean) * rstd, g.y, bb.y);
            y.z = fmaf((o[i*4+2] - mean) * rstd, g.z, bb.z);
            y.w = fmaf((o[i*4+3] - mean) * rstd, g.w, bb.w);
            __stcs(&orow[cb4 + i], y);   // write-once streaming store
        }
    }
}

extern "C" void kernel_launch(void* const* d_in, const int* in_sizes, int n_in,
                              void* d_out, int out_size)
{
    const float* query = (const float*)d_in[0];
    const float* value = (const float*)d_in[1];
    const float* W_w   = (const float*)d_in[2];
    const float* b_w   = (const float*)d_in[3];
    const float* gamma = (const float*)d_in[4];
    const float* beta  = (const float*)d_in[5];
    float* out = (float*)d_out;

    dydw_fused_kernel<<<GRID_1WAVE, 256>>>(query, value, W_w, b_w, gamma, beta, out);
}

// round 13
// speedup vs baseline: 1.3715x; 1.0758x over previous
#include <cuda_runtime.h>

// DyDepthwiseConvAtten: B=1024, N=100, C=256, K=3 — fused, one wave.
// R13: CONTIGUOUS lane mapping. Lane l owns channels [4l,4l+4) (chunk A)
// and [128+4l,128+4l+4) (chunk B), so every LDG.128/STG.128 instruction is
// a contiguous 512B warp access (4 L1 wavefronts, not 8 as with the old
// interleaved lane*2 mapping). Halo needs 6 SHFL (extra pair at ch 127/128).

#define ROWS_TOTAL (1024 * 100)
#define CH 256
#define LN_EPS 1e-5f
#define GRID_1WAVE 740

__global__ __launch_bounds__(256, 5)
void dydw_fused_kernel(const float* __restrict__ query,
                       const float* __restrict__ value,
                       const float* __restrict__ W_w,
                       const float* __restrict__ b_w,
                       const float* __restrict__ gamma,
                       const float* __restrict__ beta,
                       float* __restrict__ out)
{
    const int lane   = threadIdx.x & 31;
    const int warp   = (blockIdx.x * blockDim.x + threadIdx.x) >> 5;
    const int nwarps = (gridDim.x * blockDim.x) >> 5;   // 5920

    const int grp = lane >> 3;          // 8-lane group: which tap it finishes
    const float bias = (grp < 3) ? __ldg(&b_w[grp]) : 0.0f;

    // W_w is [3][256] floats = 64 float4 per tap; lane's chunks at f4 idx
    // lane and 32+lane within each tap.
    const float4* Wf4 = (const float4*)W_w;

    for (int row = warp; row < ROWS_TOTAL; row += nwarps) {
        const float4* qrow = (const float4*)(query + (size_t)row * CH);
        const float4* vrow = (const float4*)(value + (size_t)row * CH);
        // contiguous warp accesses: instr covers f4[0..31] / f4[32..63]
        const float4 qA = qrow[lane];
        const float4 qB = qrow[32 + lane];
        const float4 vA = vrow[lane];
        const float4 vB = vrow[32 + lane];

        // ---- dynamic taps: s_k = q · W_k over this lane's 8 channels ----
        float s0, s1, s2;
        {
            const float4 a0 = __ldg(&Wf4[lane]),        a1 = __ldg(&Wf4[32 + lane]);
            const float4 b0 = __ldg(&Wf4[64 + lane]),   b1 = __ldg(&Wf4[96 + lane]);
            const float4 c0 = __ldg(&Wf4[128 + lane]),  c1 = __ldg(&Wf4[160 + lane]);
            s0 = fmaf(qA.x, a0.x, fmaf(qA.y, a0.y, fmaf(qA.z, a0.z, qA.w * a0.w)));
            s0 = fmaf(qB.x, a1.x, fmaf(qB.y, a1.y, fmaf(qB.z, a1.z, fmaf(qB.w, a1.w, s0))));
            s1 = fmaf(qA.x, b0.x, fmaf(qA.y, b0.y, fmaf(qA.z, b0.z, qA.w * b0.w)));
            s1 = fmaf(qB.x, b1.x, fmaf(qB.y, b1.y, fmaf(qB.z, b1.z, fmaf(qB.w, b1.w, s1))));
            s2 = fmaf(qA.x, c0.x, fmaf(qA.y, c0.y, fmaf(qA.z, c0.z, qA.w * c0.w)));
            s2 = fmaf(qB.x, c1.x, fmaf(qB.y, c1.y, fmaf(qB.z, c1.z, fmaf(qB.w, c1.w, s2))));
        }
        // butterfly {16,8} -> mod-8 class partials; 8-lane groups finish one tap
        #pragma unroll
        for (int off = 16; off >= 8; off >>= 1) {
            s0 += __shfl_xor_sync(0xffffffffu, s0, off);
            s1 += __shfl_xor_sync(0xffffffffu, s1, off);
            s2 += __shfl_xor_sync(0xffffffffu, s2, off);
        }
        float t = (grp == 0) ? s0 : (grp == 1) ? s1 : (grp == 2) ? s2 : s0;
        t += __shfl_xor_sync(0xffffffffu, t, 4);
        t += __shfl_xor_sync(0xffffffffu, t, 2);
        t += __shfl_xor_sync(0xffffffffu, t, 1);
        t += bias;
        const float k0 = __shfl_sync(0xffffffffu, t, 0);
        const float k1 = __shfl_sync(0xffffffffu, t, 8);
        const float k2 = __shfl_sync(0xffffffffu, t, 16);

        // ---- halo exchange (6 SHFL) ----
        // chunk A = ch[4l .. 4l+3], chunk B = ch[128+4l .. 128+4l+3]
        float leftA  = __shfl_up_sync(0xffffffffu, vA.w, 1);    // ch 4l-1
        float rightA = __shfl_down_sync(0xffffffffu, vA.x, 1);  // ch 4l+4
        float leftB  = __shfl_up_sync(0xffffffffu, vB.w, 1);    // ch 128+4l-1
        float rightB = __shfl_down_sync(0xffffffffu, vB.x, 1);  // ch 128+4l+4
        const float bx0  = __shfl_sync(0xffffffffu, vB.x, 0);   // ch 128
        const float aw31 = __shfl_sync(0xffffffffu, vA.w, 31);  // ch 127
        if (lane == 0)  { leftA = 0.f; leftB = aw31; }
        if (lane == 31) { rightA = bx0; rightB = 0.f; }

        // ---- 3-tap conv + accumulate LN stats ----
        const float a4[4] = {vA.x, vA.y, vA.z, vA.w};
        const float b4[4] = {vB.x, vB.y, vB.z, vB.w};
        float oA[4], oB[4];
        float sum = 0.f, sq = 0.f;
        #pragma unroll
        for (int i = 0; i < 4; i++) {
            const float vmA = (i == 0) ? leftA  : a4[i - 1];
            const float vpA = (i == 3) ? rightA : a4[i + 1];
            oA[i] = fmaf(k0, vmA, fmaf(k1, a4[i], k2 * vpA));
            sum += oA[i];
            sq = fmaf(oA[i], oA[i], sq);
            const float vmB = (i == 0) ? leftB  : b4[i - 1];
            const float vpB = (i == 3) ? rightB : b4[i + 1];
            oB[i] = fmaf(k0, vmB, fmaf(k1, b4[i], k2 * vpB));
            sum += oB[i];
            sq = fmaf(oB[i], oB[i], sq);
        }

        // ---- LayerNorm reduce: grouped 2-value butterfly (8 SHFL) ----
        const float pa = sum + __shfl_xor_sync(0xffffffffu, sum, 16);
        const float pb = sq  + __shfl_xor_sync(0xffffffffu, sq,  16);
        float r = (lane < 16) ? pa : pb;
        #pragma unroll
        for (int off = 8; off; off >>= 1)
            r += __shfl_xor_sync(0xffffffffu, r, off);
        const float tot_sum = __shfl_sync(0xffffffffu, r, 0);
        const float tot_sq  = __shfl_sync(0xffffffffu, r, 16);

        const float mean = tot_sum * (1.f / CH);
        const float var  = tot_sq * (1.f / CH) - mean * mean;
        const float rstd = rsqrtf(var + LN_EPS);

        // ---- normalize + affine; gamma/beta from L1, contiguous ----
        const float4 gA = __ldg((const float4*)gamma + lane);
        const float4 gB = __ldg((const float4*)gamma + 32 + lane);
        const float4 bA = __ldg((const float4*)beta + lane);
        const float4 bB = __ldg((const float4*)beta + 32 + lane);

        float4 yA, yB;
        yA.x = fmaf((oA[0] - mean) * rstd, gA.x, bA.x);
        yA.y = fmaf((oA[1] - mean) * rstd, gA.y, bA.y);
        yA.z = fmaf((oA[2] - mean) * rstd, gA.z, bA.z);
        yA.w = fmaf((oA[3] - mean) * rstd, gA.w, bA.w);
        yB.x = fmaf((oB[0] - mean) * rstd, gB.x, bB.x);
        yB.y = fmaf((oB[1] - mean) * rstd, gB.y, bB.y);
        yB.z = fmaf((oB[2] - mean) * rstd, gB.z, bB.z);
        yB.w = fmaf((oB[3] - mean) * rstd, gB.w, bB.w);

        float4* orow = (float4*)(out + (size_t)row * CH);
        __stcs(&orow[lane], yA);
        __stcs(&orow[32 + lane], yB);
    }
}

extern "C" void kernel_launch(void* const* d_in, const int* in_sizes, int n_in,
                              void* d_out, int out_size)
{
    const float* query = (const float*)d_in[0];
    const float* value = (const float*)d_in[1];
    const float* W_w   = (const float*)d_in[2];
    const float* b_w   = (const float*)d_in[3];
    const float* gamma = (const float*)d_in[4];
    const float* beta  = (const float*)d_in[5];
    float* out = (float*)d_out;

    dydw_fused_kernel<<<GRID_1WAVE, 256>>>(query, value, W_w, b_w, gamma, beta, out);
}

// round 14
// speedup vs baseline: 1.4158x; 1.0323x over previous
#include <cuda_runtime.h>

// DyDepthwiseConvAtten: B=1024, N=100, C=256, K=3 — fused, one wave.
// R14: TWO adjacent rows per warp iteration. All reduce chains duplicated
// and independent -> SHFL dependency bubbles of row0 fill with row1 work.
// Contiguous lane mapping (R13): lane l owns ch [4l,4l+4) and [128+4l,..).
// v loads issued after q dies; q-dot reduce hides v latency.

#define ROWS_TOTAL (1024 * 100)
#define CH 256
#define LN_EPS 1e-5f
#define GRID_1WAVE 592   // 148 SM x 4 blocks (<=64 regs)

__device__ __forceinline__ float dot4(float4 a, float4 b, float acc) {
    return fmaf(a.x, b.x, fmaf(a.y, b.y, fmaf(a.z, b.z, fmaf(a.w, b.w, acc))));
}

__global__ __launch_bounds__(256, 4)
void dydw_fused_kernel(const float* __restrict__ query,
                       const float* __restrict__ value,
                       const float* __restrict__ W_w,
                       const float* __restrict__ b_w,
                       const float* __restrict__ gamma,
                       const float* __restrict__ beta,
                       float* __restrict__ out)
{
    const int lane   = threadIdx.x & 31;
    const int warp   = (blockIdx.x * blockDim.x + threadIdx.x) >> 5;
    const int nwarps = (gridDim.x * blockDim.x) >> 5;   // 4736

    const int grp = lane >> 3;
    const float bias = (grp < 3) ? __ldg(&b_w[grp]) : 0.0f;
    const float4* Wf4 = (const float4*)W_w;   // [3][64] float4

    // pairs of adjacent rows; rp always even so (rp, rp+1) valid when rp < ROWS
    for (int rp = warp * 2; rp < ROWS_TOTAL; rp += 2 * nwarps) {
        const float4* q0p = (const float4*)(query + (size_t)rp * CH);
        const float4* q1p = q0p + 64;   // row rp+1 (adjacent)
        const float4 qA0 = q0p[lane], qB0 = q0p[32 + lane];
        const float4 qA1 = q1p[lane], qB1 = q1p[32 + lane];

        // ---- dots for both rows; W in two halves to cap live regs ----
        float s00, s10, s20, s01, s11, s21;
        {
            const float4 a0 = __ldg(&Wf4[lane]);
            const float4 b0 = __ldg(&Wf4[64 + lane]);
            const float4 c0 = __ldg(&Wf4[128 + lane]);
            s00 = dot4(qA0, a0, 0.f); s10 = dot4(qA0, b0, 0.f); s20 = dot4(qA0, c0, 0.f);
            s01 = dot4(qA1, a0, 0.f); s11 = dot4(qA1, b0, 0.f); s21 = dot4(qA1, c0, 0.f);
        }
        {
            const float4 a1 = __ldg(&Wf4[32 + lane]);
            const float4 b1 = __ldg(&Wf4[96 + lane]);
            const float4 c1 = __ldg(&Wf4[160 + lane]);
            s00 = dot4(qB0, a1, s00); s10 = dot4(qB0, b1, s10); s20 = dot4(qB0, c1, s20);
            s01 = dot4(qB1, a1, s01); s11 = dot4(qB1, b1, s11); s21 = dot4(qB1, c1, s21);
        }

        // ---- v loads now: latency hidden behind the 24-SHFL reduce below ----
        const float4* v0p = (const float4*)(value + (size_t)rp * CH);
        const float4* v1p = v0p + 64;
        const float4 vA0 = v0p[lane], vB0 = v0p[32 + lane];
        const float4 vA1 = v1p[lane], vB1 = v1p[32 + lane];

        // ---- tap reduce: butterfly {16,8} on 6 values, two indep finishes ----
        #pragma unroll
        for (int off = 16; off >= 8; off >>= 1) {
            s00 += __shfl_xor_sync(0xffffffffu, s00, off);
            s01 += __shfl_xor_sync(0xffffffffu, s01, off);
            s10 += __shfl_xor_sync(0xffffffffu, s10, off);
            s11 += __shfl_xor_sync(0xffffffffu, s11, off);
            s20 += __shfl_xor_sync(0xffffffffu, s20, off);
            s21 += __shfl_xor_sync(0xffffffffu, s21, off);
        }
        float t0 = (grp == 0) ? s00 : (grp == 1) ? s10 : (grp == 2) ? s20 : s00;
        float t1 = (grp == 0) ? s01 : (grp == 1) ? s11 : (grp == 2) ? s21 : s01;
        #pragma unroll
        for (int off = 4; off; off >>= 1) {
            t0 += __shfl_xor_sync(0xffffffffu, t0, off);
            t1 += __shfl_xor_sync(0xffffffffu, t1, off);
        }
        t0 += bias; t1 += bias;
        const float k00 = __shfl_sync(0xffffffffu, t0, 0);
        const float k10 = __shfl_sync(0xffffffffu, t0, 8);
        const float k20 = __shfl_sync(0xffffffffu, t0, 16);
        const float k01 = __shfl_sync(0xffffffffu, t1, 0);
        const float k11 = __shfl_sync(0xffffffffu, t1, 8);
        const float k21 = __shfl_sync(0xffffffffu, t1, 16);

        // ---- halos, both rows (independent chains) ----
        float lA0 = __shfl_up_sync(0xffffffffu, vA0.w, 1);
        float rA0 = __shfl_down_sync(0xffffffffu, vA0.x, 1);
        float lB0 = __shfl_up_sync(0xffffffffu, vB0.w, 1);
        float rB0 = __shfl_down_sync(0xffffffffu, vB0.x, 1);
        float lA1 = __shfl_up_sync(0xffffffffu, vA1.w, 1);
        float rA1 = __shfl_down_sync(0xffffffffu, vA1.x, 1);
        float lB1 = __shfl_up_sync(0xffffffffu, vB1.w, 1);
        float rB1 = __shfl_down_sync(0xffffffffu, vB1.x, 1);
        const float m0 = __shfl_sync(0xffffffffu, vB0.x, 0);    // row0 ch128
        const float p0 = __shfl_sync(0xffffffffu, vA0.w, 31);   // row0 ch127
        const float m1 = __shfl_sync(0xffffffffu, vB1.x, 0);
        const float p1 = __shfl_sync(0xffffffffu, vA1.w, 31);
        if (lane == 0)  { lA0 = 0.f; lB0 = p0; lA1 = 0.f; lB1 = p1; }
        if (lane == 31) { rA0 = m0; rB0 = 0.f; rA1 = m1; rB1 = 0.f; }

        // ---- conv + LN stats, both rows ----
        float oA0[4], oB0[4], oA1[4], oB1[4];
        float sum0 = 0.f, sq0 = 0.f, sum1 = 0.f, sq1 = 0.f;
        {
            const float a[4] = {vA0.x, vA0.y, vA0.z, vA0.w};
            const float b[4] = {vB0.x, vB0.y, vB0.z, vB0.w};
            #pragma unroll
            for (int i = 0; i < 4; i++) {
                const float vmA = (i == 0) ? lA0 : a[i-1];
                const float vpA = (i == 3) ? rA0 : a[i+1];
                oA0[i] = fmaf(k00, vmA, fmaf(k10, a[i], k20 * vpA));
                sum0 += oA0[i]; sq0 = fmaf(oA0[i], oA0[i], sq0);
                const float vmB = (i == 0) ? lB0 : b[i-1];
                const float vpB = (i == 3) ? rB0 : b[i+1];
                oB0[i] = fmaf(k00, vmB, fmaf(k10, b[i], k20 * vpB));
                sum0 += oB0[i]; sq0 = fmaf(oB0[i], oB0[i], sq0);
            }
        }
        {
            const float a[4] = {vA1.x, vA1.y, vA1.z, vA1.w};
            const float b[4] = {vB1.x, vB1.y, vB1.z, vB1.w};
            #pragma unroll
            for (int i = 0; i < 4; i++) {
                const float vmA = (i == 0) ? lA1 : a[i-1];
                const float vpA = (i == 3) ? rA1 : a[i+1];
                oA1[i] = fmaf(k01, vmA, fmaf(k11, a[i], k21 * vpA));
                sum1 += oA1[i]; sq1 = fmaf(oA1[i], oA1[i], sq1);
                const float vmB = (i == 0) ? lB1 : b[i-1];
                const float vpB = (i == 3) ? rB1 : b[i+1];
                oB1[i] = fmaf(k01, vmB, fmaf(k11, b[i], k21 * vpB));
                sum1 += oB1[i]; sq1 = fmaf(oB1[i], oB1[i], sq1);
            }
        }

        // ---- LN reduce: two independent grouped butterflies ----
        const float pa0 = sum0 + __shfl_xor_sync(0xffffffffu, sum0, 16);
        const float pb0 = sq0  + __shfl_xor_sync(0xffffffffu, sq0,  16);
        const float pa1 = sum1 + __shfl_xor_sync(0xffffffffu, sum1, 16);
        const float pb1 = sq1  + __shfl_xor_sync(0xffffffffu, sq1,  16);
        float r0 = (lane < 16) ? pa0 : pb0;
        float r1 = (lane < 16) ? pa1 : pb1;
        #pragma unroll
        for (int off = 8; off; off >>= 1) {
            r0 += __shfl_xor_sync(0xffffffffu, r0, off);
            r1 += __shfl_xor_sync(0xffffffffu, r1, off);
        }
        const float mean0 = __shfl_sync(0xffffffffu, r0, 0)  * (1.f / CH);
        const float sqm0  = __shfl_sync(0xffffffffu, r0, 16) * (1.f / CH);
        const float mean1 = __shfl_sync(0xffffffffu, r1, 0)  * (1.f / CH);
        const float sqm1  = __shfl_sync(0xffffffffu, r1, 16) * (1.f / CH);
        const float rstd0 = rsqrtf(sqm0 - mean0 * mean0 + LN_EPS);
        const float rstd1 = rsqrtf(sqm1 - mean1 * mean1 + LN_EPS);

        // ---- normalize + affine; gamma/beta from L1, shared by both rows ----
        const float4 gA = __ldg((const float4*)gamma + lane);
        const float4 gB = __ldg((const float4*)gamma + 32 + lane);
        const float4 bA = __ldg((const float4*)beta + lane);
        const float4 bB = __ldg((const float4*)beta + 32 + lane);

        float4* o0p = (float4*)(out + (size_t)rp * CH);
        float4* o1p = o0p + 64;
        float4 y;
        y.x = fmaf((oA0[0] - mean0) * rstd0, gA.x, bA.x);
        y.y = fmaf((oA0[1] - mean0) * rstd0, gA.y, bA.y);
        y.z = fmaf((oA0[2] - mean0) * rstd0, gA.z, bA.z);
        y.w = fmaf((oA0[3] - mean0) * rstd0, gA.w, bA.w);
        __stcs(&o0p[lane], y);
        y.x = fmaf((oB0[0] - mean0) * rstd0, gB.x, bB.x);
        y.y = fmaf((oB0[1] - mean0) * rstd0, gB.y, bB.y);
        y.z = fmaf((oB0[2] - mean0) * rstd0, gB.z, bB.z);
        y.w = fmaf((oB0[3] - mean0) * rstd0, gB.w, bB.w);
        __stcs(&o0p[32 + lane], y);
        y.x = fmaf((oA1[0] - mean1) * rstd1, gA.x, bA.x);
        y.y = fmaf((oA1[1] - mean1) * rstd1, gA.y, bA.y);
        y.z = fmaf((oA1[2] - mean1) * rstd1, gA.z, bA.z);
        y.w = fmaf((oA1[3] - mean1) * rstd1, gA.w, bA.w);
        __stcs(&o1p[lane], y);
        y.x = fmaf((oB1[0] - mean1) * rstd1, gB.x, bB.x);
        y.y = fmaf((oB1[1] - mean1) * rstd1, gB.y, bB.y);
        y.z = fmaf((oB1[2] - mean1) * rstd1, gB.z, bB.z);
        y.w = fmaf((oB1[3] - mean1) * rstd1, gB.w, bB.w);
        __stcs(&o1p[32 + lane], y);
    }
}

extern "C" void kernel_launch(void* const* d_in, const int* in_sizes, int n_in,
                              void* d_out, int out_size)
{
    const float* query = (const float*)d_in[0];
    const float* value = (const float*)d_in[1];
    const float* W_w   = (const float*)d_in[2];
    const float* b_w   = (const float*)d_in[3];
    const float* gamma = (const float*)d_in[4];
    const float* beta  = (const float*)d_in[5];
    float* out = (float*)d_out;

    dydw_fused_kernel<<<GRID_1WAVE, 256>>>(query, value, W_w, b_w, gamma, beta, out);
}

// round 15
// speedup vs baseline: 1.4794x; 1.0449x over previous
#include <cuda_runtime.h>

// DyDepthwiseConvAtten: B=1024, N=100, C=256, K=3 — fused.
// R15: NON-PERSISTENT fine-grained launch. Block = 8 warps x 1 adjacent row
// pair = 16 rows, grid = 6400 (10.8 waves on 592 slots). HW CTA scheduler
// backfills fast SMs -> absorbs the between-SM spread floor that capped the
// one-wave persistent version at DRAM~70%. Per-row body = R14 (proven).

#define ROWS_TOTAL (1024 * 100)
#define CH 256
#define LN_EPS 1e-5f

__device__ __forceinline__ float dot4(float4 a, float4 b, float acc) {
    return fmaf(a.x, b.x, fmaf(a.y, b.y, fmaf(a.z, b.z, fmaf(a.w, b.w, acc))));
}

__global__ __launch_bounds__(256, 4)
void dydw_fused_kernel(const float* __restrict__ query,
                       const float* __restrict__ value,
                       const float* __restrict__ W_w,
                       const float* __restrict__ b_w,
                       const float* __restrict__ gamma,
                       const float* __restrict__ beta,
                       float* __restrict__ out)
{
    const int lane = threadIdx.x & 31;
    const int rp   = (blockIdx.x * 8 + (threadIdx.x >> 5)) * 2;  // adjacent pair

    const int grp = lane >> 3;
    const float bias = (grp < 3) ? __ldg(&b_w[grp]) : 0.0f;
    const float4* Wf4 = (const float4*)W_w;   // [3][64] float4

    const float4* q0p = (const float4*)(query + (size_t)rp * CH);
    const float4* q1p = q0p + 64;   // row rp+1 (adjacent)
    const float4 qA0 = q0p[lane], qB0 = q0p[32 + lane];
    const float4 qA1 = q1p[lane], qB1 = q1p[32 + lane];

    // ---- dots for both rows; W in two halves to cap live regs ----
    float s00, s10, s20, s01, s11, s21;
    {
        const float4 a0 = __ldg(&Wf4[lane]);
        const float4 b0 = __ldg(&Wf4[64 + lane]);
        const float4 c0 = __ldg(&Wf4[128 + lane]);
        s00 = dot4(qA0, a0, 0.f); s10 = dot4(qA0, b0, 0.f); s20 = dot4(qA0, c0, 0.f);
        s01 = dot4(qA1, a0, 0.f); s11 = dot4(qA1, b0, 0.f); s21 = dot4(qA1, c0, 0.f);
    }
    {
        const float4 a1 = __ldg(&Wf4[32 + lane]);
        const float4 b1 = __ldg(&Wf4[96 + lane]);
        const float4 c1 = __ldg(&Wf4[160 + lane]);
        s00 = dot4(qB0, a1, s00); s10 = dot4(qB0, b1, s10); s20 = dot4(qB0, c1, s20);
        s01 = dot4(qB1, a1, s01); s11 = dot4(qB1, b1, s11); s21 = dot4(qB1, c1, s21);
    }

    // ---- v loads now: latency hidden behind the 24-SHFL reduce below ----
    const float4* v0p = (const float4*)(value + (size_t)rp * CH);
    const float4* v1p = v0p + 64;
    const float4 vA0 = v0p[lane], vB0 = v0p[32 + lane];
    const float4 vA1 = v1p[lane], vB1 = v1p[32 + lane];

    // ---- tap reduce: butterfly {16,8} on 6 values, two indep finishes ----
    #pragma unroll
    for (int off = 16; off >= 8; off >>= 1) {
        s00 += __shfl_xor_sync(0xffffffffu, s00, off);
        s01 += __shfl_xor_sync(0xffffffffu, s01, off);
        s10 += __shfl_xor_sync(0xffffffffu, s10, off);
        s11 += __shfl_xor_sync(0xffffffffu, s11, off);
        s20 += __shfl_xor_sync(0xffffffffu, s20, off);
        s21 += __shfl_xor_sync(0xffffffffu, s21, off);
    }
    float t0 = (grp == 0) ? s00 : (grp == 1) ? s10 : (grp == 2) ? s20 : s00;
    float t1 = (grp == 0) ? s01 : (grp == 1) ? s11 : (grp == 2) ? s21 : s01;
    #pragma unroll
    for (int off = 4; off; off >>= 1) {
        t0 += __shfl_xor_sync(0xffffffffu, t0, off);
        t1 += __shfl_xor_sync(0xffffffffu, t1, off);
    }
    t0 += bias; t1 += bias;
    const float k00 = __shfl_sync(0xffffffffu, t0, 0);
    const float k10 = __shfl_sync(0xffffffffu, t0, 8);
    const float k20 = __shfl_sync(0xffffffffu, t0, 16);
    const float k01 = __shfl_sync(0xffffffffu, t1, 0);
    const float k11 = __shfl_sync(0xffffffffu, t1, 8);
    const float k21 = __shfl_sync(0xffffffffu, t1, 16);

    // ---- halos, both rows (independent chains) ----
    float lA0 = __shfl_up_sync(0xffffffffu, vA0.w, 1);
    float rA0 = __shfl_down_sync(0xffffffffu, vA0.x, 1);
    float lB0 = __shfl_up_sync(0xffffffffu, vB0.w, 1);
    float rB0 = __shfl_down_sync(0xffffffffu, vB0.x, 1);
    float lA1 = __shfl_up_sync(0xffffffffu, vA1.w, 1);
    float rA1 = __shfl_down_sync(0xffffffffu, vA1.x, 1);
    float lB1 = __shfl_up_sync(0xffffffffu, vB1.w, 1);
    float rB1 = __shfl_down_sync(0xffffffffu, vB1.x, 1);
    const float m0 = __shfl_sync(0xffffffffu, vB0.x, 0);    // row0 ch128
    const float p0 = __shfl_sync(0xffffffffu, vA0.w, 31);   // row0 ch127
    const float m1 = __shfl_sync(0xffffffffu, vB1.x, 0);
    const float p1 = __shfl_sync(0xffffffffu, vA1.w, 31);
    if (lane == 0)  { lA0 = 0.f; lB0 = p0; lA1 = 0.f; lB1 = p1; }
    if (lane == 31) { rA0 = m0; rB0 = 0.f; rA1 = m1; rB1 = 0.f; }

    // ---- conv + LN stats, both rows ----
    float oA0[4], oB0[4], oA1[4], oB1[4];
    float sum0 = 0.f, sq0 = 0.f, sum1 = 0.f, sq1 = 0.f;
    {
        const float a[4] = {vA0.x, vA0.y, vA0.z, vA0.w};
        const float b[4] = {vB0.x, vB0.y, vB0.z, vB0.w};
        #pragma unroll
        for (int i = 0; i < 4; i++) {
            const float vmA = (i == 0) ? lA0 : a[i-1];
            const float vpA = (i == 3) ? rA0 : a[i+1];
            oA0[i] = fmaf(k00, vmA, fmaf(k10, a[i], k20 * vpA));
            sum0 += oA0[i]; sq0 = fmaf(oA0[i], oA0[i], sq0);
            const float vmB = (i == 0) ? lB0 : b[i-1];
            const float vpB = (i == 3) ? rB0 : b[i+1];
            oB0[i] = fmaf(k00, vmB, fmaf(k10, b[i], k20 * vpB));
            sum0 += oB0[i]; sq0 = fmaf(oB0[i], oB0[i], sq0);
        }
    }
    {
        const float a[4] = {vA1.x, vA1.y, vA1.z, vA1.w};
        const float b[4] = {vB1.x, vB1.y, vB1.z, vB1.w};
        #pragma unroll
        for (int i = 0; i < 4; i++) {
            const float vmA = (i == 0) ? lA1 : a[i-1];
            const float vpA = (i == 3) ? rA1 : a[i+1];
            oA1[i] = fmaf(k01, vmA, fmaf(k11, a[i], k21 * vpA));
            sum1 += oA1[i]; sq1 = fmaf(oA1[i], oA1[i], sq1);
            const float vmB = (i == 0) ? lB1 : b[i-1];
            const float vpB = (i == 3) ? rB1 : b[i+1];
            oB1[i] = fmaf(k01, vmB, fmaf(k11, b[i], k21 * vpB));
            sum1 += oB1[i]; sq1 = fmaf(oB1[i], oB1[i], sq1);
        }
    }

    // ---- LN reduce: two independent grouped butterflies ----
    const float pa0 = sum0 + __shfl_xor_sync(0xffffffffu, sum0, 16);
    const float pb0 = sq0  + __shfl_xor_sync(0xffffffffu, sq0,  16);
    const float pa1 = sum1 + __shfl_xor_sync(0xffffffffu, sum1, 16);
    const float pb1 = sq1  + __shfl_xor_sync(0xffffffffu, sq1,  16);
    float r0 = (lane < 16) ? pa0 : pb0;
    float r1 = (lane < 16) ? pa1 : pb1;
    #pragma unroll
    for (int off = 8; off; off >>= 1) {
        r0 += __shfl_xor_sync(0xffffffffu, r0, off);
        r1 += __shfl_xor_sync(0xffffffffu, r1, off);
    }
    const float mean0 = __shfl_sync(0xffffffffu, r0, 0)  * (1.f / CH);
    const float sqm0  = __shfl_sync(0xffffffffu, r0, 16) * (1.f / CH);
    const float mean1 = __shfl_sync(0xffffffffu, r1, 0)  * (1.f / CH);
    const float sqm1  = __shfl_sync(0xffffffffu, r1, 16) * (1.f / CH);
    const float rstd0 = rsqrtf(sqm0 - mean0 * mean0 + LN_EPS);
    const float rstd1 = rsqrtf(sqm1 - mean1 * mean1 + LN_EPS);

    // ---- normalize + affine; gamma/beta from L1, shared by both rows ----
    const float4 gA = __ldg((const float4*)gamma + lane);
    const float4 gB = __ldg((const float4*)gamma + 32 + lane);
    const float4 bA = __ldg((const float4*)beta + lane);
    const float4 bB = __ldg((const float4*)beta + 32 + lane);

    float4* o0p = (float4*)(out + (size_t)rp * CH);
    float4* o1p = o0p + 64;
    float4 y;
    y.x = fmaf((oA0[0] - mean0) * rstd0, gA.x, bA.x);
    y.y = fmaf((oA0[1] - mean0) * rstd0, gA.y, bA.y);
    y.z = fmaf((oA0[2] - mean0) * rstd0, gA.z, bA.z);
    y.w = fmaf((oA0[3] - mean0) * rstd0, gA.w, bA.w);
    __stcs(&o0p[lane], y);
    y.x = fmaf((oB0[0] - mean0) * rstd0, gB.x, bB.x);
    y.y = fmaf((oB0[1] - mean0) * rstd0, gB.y, bB.y);
    y.z = fmaf((oB0[2] - mean0) * rstd0, gB.z, bB.z);
    y.w = fmaf((oB0[3] - mean0) * rstd0, gB.w, bB.w);
    __stcs(&o0p[32 + lane], y);
    y.x = fmaf((oA1[0] - mean1) * rstd1, gA.x, bA.x);
    y.y = fmaf((oA1[1] - mean1) * rstd1, gA.y, bA.y);
    y.z = fmaf((oA1[2] - mean1) * rstd1, gA.z, bA.z);
    y.w = fmaf((oA1[3] - mean1) * rstd1, gA.w, bA.w);
    __stcs(&o1p[lane], y);
    y.x = fmaf((oB1[0] - mean1) * rstd1, gB.x, bB.x);
    y.y = fmaf((oB1[1] - mean1) * rstd1, gB.y, bB.y);
    y.z = fmaf((oB1[2] - mean1) * rstd1, gB.z, bB.z);
    y.w = fmaf((oB1[3] - mean1) * rstd1, gB.w, bB.w);
    __stcs(&o1p[32 + lane], y);
}

extern "C" void kernel_launch(void* const* d_in, const int* in_sizes, int n_in,
                              void* d_out, int out_size)
{
    const float* query = (const float*)d_in[0];
    const float* value = (const float*)d_in[1];
    const float* W_w   = (const float*)d_in[2];
    const float* b_w   = (const float*)d_in[3];
    const float* gamma = (const float*)d_in[4];
    const float* beta  = (const float*)d_in[5];
    float* out = (float*)d_out;

    // 6400 blocks x 16 rows each = 102400 rows; ~10.8 waves on 592 slots,
    // HW scheduler backfills -> dynamic balancing, ~2% quantization.
    dydw_fused_kernel<<<ROWS_TOTAL / 16, 256>>>(query, value, W_w, b_w, gamma, beta, out);
}